// round 1
// baseline (speedup 1.0000x reference)
#include <cuda_runtime.h>
#include <cuda_bf16.h>
#include <cstdint>

#define N_NODES 102400
#define N_EDGES 1638400
#define BATCH   1024

// ---------------- scratch (device globals: no allocation allowed) ----------
__device__ float g_h1 [N_NODES * 96];
__device__ float g_as1[N_NODES * 6];
__device__ float g_ad1[N_NODES * 6];
__device__ float g_t1 [N_NODES * 96];
__device__ float g_h2 [N_NODES * 32];
__device__ float g_as2[N_NODES];
__device__ float g_ad2[N_NODES];
__device__ int   g_count [N_NODES];
__device__ int   g_rowptr[N_NODES + 1];
__device__ int   g_cursor[N_NODES];
__device__ int   g_esrc  [N_EDGES];
__device__ float g_out2[BATCH * 32];
__device__ float g_GI  [BATCH * 192];
__device__ float g_HS  [BATCH * 64];

// ---------------- math helpers --------------------------------------------
__device__ __forceinline__ float sigm_f(float x) {
    return 1.0f / (1.0f + __expf(-x));
}
__device__ __forceinline__ float tanh_f(float x) {
    float cx = fminf(fmaxf(x, -15.0f), 15.0f);
    float e  = __expf(2.0f * cx);
    return (e - 1.0f) / (e + 1.0f);
}
__device__ __forceinline__ float lrelu02(float x) {
    return x > 0.0f ? x : 0.2f * x;
}

// ---------------- K0: zero degree counters ---------------------------------
__global__ void k0_zero() {
    int i = blockIdx.x * blockDim.x + threadIdx.x;
    if (i < N_NODES) g_count[i] = 0;
}

// ---------------- K1: GAT1 node transform: h1 = x@W.T, a_src/a_dst dots ----
__global__ void k1_node1(const float* __restrict__ x,
                         const float* __restrict__ W,   // [96,4]
                         const float* __restrict__ as_, // [6,16]
                         const float* __restrict__ ad_) // [6,16]
{
    __shared__ float sW[384], sas[96], sad[96];
    int tid = threadIdx.x;
    for (int i = tid; i < 384; i += blockDim.x) sW[i] = W[i];
    for (int i = tid; i < 96;  i += blockDim.x) { sas[i] = as_[i]; sad[i] = ad_[i]; }
    __syncthreads();

    int n = blockIdx.x * blockDim.x + tid;
    if (n >= N_NODES) return;
    float4 xv = *(const float4*)(x + (size_t)n * 4);

    #pragma unroll
    for (int h = 0; h < 6; h++) {
        float accs = 0.f, accd = 0.f;
        float4 o;
        #pragma unroll
        for (int f = 0; f < 16; f++) {
            int j = h * 16 + f;
            float v = xv.x * sW[j*4+0] + xv.y * sW[j*4+1] + xv.z * sW[j*4+2] + xv.w * sW[j*4+3];
            accs += v * sas[j];
            accd += v * sad[j];
            ((float*)&o)[f & 3] = v;
            if ((f & 3) == 3)
                *(float4*)(g_h1 + (size_t)n * 96 + h * 16 + (f - 3)) = o;
        }
        g_as1[n * 6 + h] = accs;
        g_ad1[n * 6 + h] = accd;
    }
}

// ---------------- K2: per-dst degree count ---------------------------------
__global__ void k2_count(const int* __restrict__ dst) {
    int i = blockIdx.x * blockDim.x + threadIdx.x;
    if (i < N_EDGES) atomicAdd(&g_count[dst[i]], 1);
}

// ---------------- K3: exclusive scan over 102400 counters (1 block) --------
__global__ void k3_scan() {
    __shared__ int sh[1024];
    int t = threadIdx.x;
    int base = t * 100;           // 1024 * 100 == N_NODES
    int s = 0;
    for (int i = 0; i < 100; i++) s += g_count[base + i];
    sh[t] = s;
    __syncthreads();
    for (int off = 1; off < 1024; off <<= 1) {
        int v = (t >= off) ? sh[t - off] : 0;
        __syncthreads();
        sh[t] += v;
        __syncthreads();
    }
    int run = sh[t] - s;          // exclusive offset for this chunk
    for (int i = 0; i < 100; i++) {
        g_rowptr[base + i] = run;
        g_cursor[base + i] = run;
        run += g_count[base + i];
    }
    if (t == 1023) g_rowptr[N_NODES] = run;
}

// ---------------- K4: scatter edge srcs into CSR by dst --------------------
__global__ void k4_scatter(const int* __restrict__ src, const int* __restrict__ dst) {
    int i = blockIdx.x * blockDim.x + threadIdx.x;
    if (i < N_EDGES) {
        int d = dst[i];
        int p = atomicAdd(&g_cursor[d], 1);
        g_esrc[p] = src[i];
    }
}

// ---------------- K5: GAT1 edge aggregation + softmax + tanh (warp/dst) ----
__global__ void k5_agg1(const float* __restrict__ b1) {
    int gw   = (blockIdx.x * blockDim.x + threadIdx.x) >> 5;
    int lane = threadIdx.x & 31;
    if (gw >= N_NODES) return;
    int d = gw;

    float adv = (lane < 6) ? g_ad1[d * 6 + lane] : 0.f;
    int h0 = lane >> 4, h1 = 2 + h0, h2 = 4 + h0;

    float acc0 = 0.f, acc1 = 0.f, acc2 = 0.f, den = 0.f;
    int beg = g_rowptr[d], end = g_rowptr[d + 1];

    for (int e = beg - 1; e < end; ++e) {       // e == beg-1 -> self loop
        int s = (e < beg) ? d : g_esrc[e];
        float asv = (lane < 6) ? g_as1[s * 6 + lane] : 0.f;
        float wl  = __expf(lrelu02(asv + adv));
        if (lane < 6) den += wl;
        float w0 = __shfl_sync(0xffffffffu, wl, h0);
        float w1 = __shfl_sync(0xffffffffu, wl, h1);
        float w2 = __shfl_sync(0xffffffffu, wl, h2);
        const float* hp = g_h1 + (size_t)s * 96;
        acc0 += w0 * hp[lane];
        acc1 += w1 * hp[lane + 32];
        acc2 += w2 * hp[lane + 64];
    }
    float d0 = __shfl_sync(0xffffffffu, den, h0);
    float d1 = __shfl_sync(0xffffffffu, den, h1);
    float d2 = __shfl_sync(0xffffffffu, den, h2);

    float* out = g_t1 + (size_t)d * 96;
    out[lane]      = tanh_f(acc0 / d0 + b1[lane]);
    out[lane + 32] = tanh_f(acc1 / d1 + b1[lane + 32]);
    out[lane + 64] = tanh_f(acc2 / d2 + b1[lane + 64]);
}

// ---------------- K6: GAT2 node transform: h2 = t1@W2.T, attn dots ---------
__global__ void k6_node2(const float* __restrict__ W2,   // [32,96]
                         const float* __restrict__ as2w, // [1,32]
                         const float* __restrict__ ad2w) // [1,32]
{
    __shared__ float sWt[96 * 32];
    __shared__ float sas[32], sad[32];
    int tid = threadIdx.x;
    for (int i = tid; i < 3072; i += blockDim.x) {
        int j = i / 96, k = i % 96;
        sWt[k * 32 + j] = W2[i];
    }
    if (tid < 32) { sas[tid] = as2w[tid]; sad[tid] = ad2w[tid]; }
    __syncthreads();

    int n = blockIdx.x * blockDim.x + tid;
    if (n >= N_NODES) return;

    float acc[32];
    #pragma unroll
    for (int j = 0; j < 32; j++) acc[j] = 0.f;

    const float4* trow = (const float4*)(g_t1 + (size_t)n * 96);
    #pragma unroll 2
    for (int k4 = 0; k4 < 24; k4++) {
        float4 tv = trow[k4];
        int k = k4 * 4;
        #pragma unroll
        for (int j = 0; j < 32; j++) acc[j] += tv.x * sWt[(k + 0) * 32 + j];
        #pragma unroll
        for (int j = 0; j < 32; j++) acc[j] += tv.y * sWt[(k + 1) * 32 + j];
        #pragma unroll
        for (int j = 0; j < 32; j++) acc[j] += tv.z * sWt[(k + 2) * 32 + j];
        #pragma unroll
        for (int j = 0; j < 32; j++) acc[j] += tv.w * sWt[(k + 3) * 32 + j];
    }

    float as = 0.f, ad = 0.f;
    #pragma unroll
    for (int j = 0; j < 32; j++) { as += acc[j] * sas[j]; ad += acc[j] * sad[j]; }

    float* h2 = g_h2 + (size_t)n * 32;
    #pragma unroll
    for (int q = 0; q < 8; q++) {
        float4 o = make_float4(acc[4*q], acc[4*q+1], acc[4*q+2], acc[4*q+3]);
        ((float4*)h2)[q] = o;
    }
    g_as2[n] = as;
    g_ad2[n] = ad;
}

// ---------------- K7: GAT2 aggregation at robot nodes only (warp/robot) ----
__global__ void k7_agg2(const int* __restrict__ robot_index,
                        const float* __restrict__ b2) {
    int gw   = (blockIdx.x * blockDim.x + threadIdx.x) >> 5;
    int lane = threadIdx.x & 31;
    if (gw >= BATCH) return;
    int r = robot_index[gw];

    float adv = g_ad2[r];
    float acc = 0.f, den = 0.f;
    int beg = g_rowptr[r], end = g_rowptr[r + 1];
    for (int e = beg - 1; e < end; ++e) {
        int s = (e < beg) ? r : g_esrc[e];
        float w = __expf(lrelu02(g_as2[s] + adv));
        den += w;
        acc += w * g_h2[(size_t)s * 32 + lane];
    }
    g_out2[gw * 32 + lane] = acc / den + b2[lane];
}

// ---------------- K8: fc1 (tanh) + GRU input gates GI (per robot) ----------
__global__ void k8_fc1_gi(const float* __restrict__ robot_feat, // [B,4]
                          const float* __restrict__ fc1W,       // [64,36]
                          const float* __restrict__ fc1b,       // [64]
                          const float* __restrict__ wih,        // [192,64]
                          const float* __restrict__ bih)        // [192]
{
    __shared__ float s_in[36];
    __shared__ float s_x[64];
    int b = blockIdx.x, tid = threadIdx.x;
    if (tid < 32)       s_in[tid] = g_out2[b * 32 + tid];
    else if (tid < 36)  s_in[tid] = robot_feat[b * 4 + (tid - 32)];
    __syncthreads();
    if (tid < 64) {
        float a = fc1b[tid];
        const float* wr = fc1W + tid * 36;
        #pragma unroll
        for (int k = 0; k < 36; k++) a += s_in[k] * wr[k];
        s_x[tid] = tanh_f(a);
    }
    __syncthreads();
    {
        float a = bih[tid];
        const float* wr = wih + tid * 64;
        #pragma unroll 8
        for (int k = 0; k < 64; k++) a += s_x[k] * wr[k];
        g_GI[b * 192 + tid] = a;
    }
}

// ---------------- K9: sequential GRU over 1024 steps (1 block) -------------
__global__ void __launch_bounds__(192, 1) k9_gru(const float* __restrict__ whh, // [192,64]
                                                 const float* __restrict__ bhh) // [192]
{
    __shared__ __align__(16) float s_h[64];
    __shared__ float s_r[64], s_z[64], s_in[64], s_hn[64];
    int j = threadIdx.x;

    float w[64];
    #pragma unroll
    for (int k = 0; k < 64; k++) w[k] = whh[j * 64 + k];
    float bh = bhh[j];

    float hp = 0.f;
    if (j < 64) s_h[j] = 0.f;
    __syncthreads();

    const float4* h4 = (const float4*)s_h;
    for (int t = 0; t < BATCH; t++) {
        float gi = g_GI[t * 192 + j];
        float a0 = bh, a1 = 0.f, a2 = 0.f, a3 = 0.f;
        #pragma unroll
        for (int k4 = 0; k4 < 16; k4++) {
            float4 hv = h4[k4];
            a0 += hv.x * w[k4 * 4 + 0];
            a1 += hv.y * w[k4 * 4 + 1];
            a2 += hv.z * w[k4 * 4 + 2];
            a3 += hv.w * w[k4 * 4 + 3];
        }
        float gh = (a0 + a1) + (a2 + a3);

        if (j < 64)          s_r[j]       = sigm_f(gi + gh);
        else if (j < 128)    s_z[j - 64]  = sigm_f(gi + gh);
        else               { s_in[j - 128] = gi; s_hn[j - 128] = gh; }
        __syncthreads();

        if (j < 64) {
            float ng = tanh_f(s_in[j] + s_r[j] * s_hn[j]);
            float z  = s_z[j];
            hp = (1.f - z) * ng + z * hp;
            g_HS[t * 64 + j] = hp;
            s_h[j] = hp;
        }
        __syncthreads();
    }
}

// ---------------- K10: fc2 -------------------------------------------------
__global__ void k10_fc2(const float* __restrict__ W,  // [11,64]
                        const float* __restrict__ b,  // [11]
                        float* __restrict__ out) {
    int i = blockIdx.x * blockDim.x + threadIdx.x;
    if (i >= BATCH * 11) return;
    int bb = i / 11, o = i % 11;
    float a = b[o];
    const float* hr = g_HS + bb * 64;
    const float* wr = W + o * 64;
    #pragma unroll
    for (int k = 0; k < 64; k++) a += hr[k] * wr[k];
    out[i] = a;
}

// ---------------- launch ----------------------------------------------------
extern "C" void kernel_launch(void* const* d_in, const int* in_sizes, int n_in,
                              void* d_out, int out_size) {
    const float* x              = (const float*)d_in[0];
    const int*   ei             = (const int*)  d_in[1];
    const int*   src            = ei;
    const int*   dst            = ei + N_EDGES;
    const int*   robot_index    = (const int*)  d_in[2];
    const float* robot_features = (const float*)d_in[3];
    const float* c1_W  = (const float*)d_in[4];
    const float* c1_as = (const float*)d_in[5];
    const float* c1_ad = (const float*)d_in[6];
    const float* c1_b  = (const float*)d_in[7];
    const float* c2_W  = (const float*)d_in[8];
    const float* c2_as = (const float*)d_in[9];
    const float* c2_ad = (const float*)d_in[10];
    const float* c2_b  = (const float*)d_in[11];
    const float* fc1_W = (const float*)d_in[12];
    const float* fc1_b = (const float*)d_in[13];
    const float* gru_wih = (const float*)d_in[14];
    const float* gru_whh = (const float*)d_in[15];
    const float* gru_bih = (const float*)d_in[16];
    const float* gru_bhh = (const float*)d_in[17];
    const float* fc2_W = (const float*)d_in[18];
    const float* fc2_b = (const float*)d_in[19];
    float* out = (float*)d_out;

    k0_zero   <<<(N_NODES + 255) / 256, 256>>>();
    k1_node1  <<<(N_NODES + 127) / 128, 128>>>(x, c1_W, c1_as, c1_ad);
    k2_count  <<<(N_EDGES + 255) / 256, 256>>>(dst);
    k3_scan   <<<1, 1024>>>();
    k4_scatter<<<(N_EDGES + 255) / 256, 256>>>(src, dst);
    k5_agg1   <<<(N_NODES * 32 + 255) / 256, 256>>>(c1_b);
    k6_node2  <<<(N_NODES + 255) / 256, 256>>>(c2_W, c2_as, c2_ad);
    k7_agg2   <<<(BATCH * 32 + 255) / 256, 256>>>(robot_index, c2_b);
    k8_fc1_gi <<<BATCH, 192>>>(robot_features, fc1_W, fc1_b, gru_wih, gru_bih);
    k9_gru    <<<1, 192>>>(gru_whh, gru_bhh);
    k10_fc2   <<<(BATCH * 11 + 255) / 256, 256>>>(fc2_W, fc2_b, out);
}

// round 2
// speedup vs baseline: 1.3195x; 1.3195x over previous
#include <cuda_runtime.h>
#include <cuda_fp16.h>
#include <cstdint>

#define N_NODES 102400
#define N_EDGES 1638400
#define BATCH   1024

typedef unsigned long long u64;

// ---------------- scratch (device globals: no allocation allowed) ----------
__device__ __half2 g_h1 [N_NODES * 48 + 64];   // fp16 node features L1 (+tail pad for OOB-safe loads)
__device__ float g_as1[N_NODES * 6];
__device__ float g_ad1[N_NODES * 6];
__device__ float g_t1 [N_NODES * 96];
__device__ float g_h2 [N_NODES * 32];
__device__ float g_as2[N_NODES];
__device__ float g_ad2[N_NODES];
__device__ int   g_count [N_NODES];
__device__ int   g_bsum  [400];
__device__ int   g_boff  [400];
__device__ int   g_rowptr[N_NODES + 1];
__device__ int   g_cursor[N_NODES];
__device__ int   g_esrc  [N_EDGES];
__device__ float g_out2[BATCH * 32];
__device__ float g_GI  [BATCH * 192];
__device__ float g_HS  [BATCH * 64];

// ---------------- math helpers --------------------------------------------
__device__ __forceinline__ float sigm_f(float x) {
    return 1.0f / (1.0f + __expf(-x));
}
__device__ __forceinline__ float tanh_f(float x) {
    float cx = fminf(fmaxf(x, -15.0f), 15.0f);
    float e  = __expf(2.0f * cx);
    return __fdividef(e - 1.0f, e + 1.0f);
}
__device__ __forceinline__ float lrelu02(float x) {
    return x > 0.0f ? x : 0.2f * x;
}
__device__ __forceinline__ u64 pack2(float x, float y) {
    u64 r;
    asm("mov.b64 %0, {%1, %2};" : "=l"(r) : "f"(x), "f"(y));
    return r;
}
__device__ __forceinline__ void fma2(u64& acc, u64 a, u64 b) {
    asm("fma.rn.f32x2 %0, %1, %2, %0;" : "+l"(acc) : "l"(a), "l"(b));
}
__device__ __forceinline__ float sum2(u64 v) {
    float x, y;
    asm("mov.b64 {%0, %1}, %2;" : "=f"(x), "=f"(y) : "l"(v));
    return x + y;
}

// ---------------- K1: GAT1 node transform (fp16 out) + zero counters -------
__global__ void k1_node1(const float* __restrict__ x,
                         const float* __restrict__ W,   // [96,4]
                         const float* __restrict__ as_, // [6,16]
                         const float* __restrict__ ad_) // [6,16]
{
    __shared__ float sW[384], sas[96], sad[96];
    int tid = threadIdx.x;
    for (int i = tid; i < 384; i += blockDim.x) sW[i] = W[i];
    for (int i = tid; i < 96;  i += blockDim.x) { sas[i] = as_[i]; sad[i] = ad_[i]; }
    __syncthreads();

    int n = blockIdx.x * blockDim.x + tid;
    if (n >= N_NODES) return;
    g_count[n] = 0;
    float4 xv = *(const float4*)(x + (size_t)n * 4);

    #pragma unroll
    for (int h = 0; h < 6; h++) {
        float accs = 0.f, accd = 0.f;
        float prev = 0.f;
        #pragma unroll
        for (int f = 0; f < 16; f++) {
            int j = h * 16 + f;
            float v = xv.x * sW[j*4+0] + xv.y * sW[j*4+1] + xv.z * sW[j*4+2] + xv.w * sW[j*4+3];
            accs += v * sas[j];
            accd += v * sad[j];
            if (f & 1) g_h1[(size_t)n * 48 + (h * 16 + f) / 2] = __floats2half2_rn(prev, v);
            else prev = v;
        }
        g_as1[n * 6 + h] = accs;
        g_ad1[n * 6 + h] = accd;
    }
}

// ---------------- K2: per-dst degree count ---------------------------------
__global__ void k2_count(const int* __restrict__ dst) {
    int i = blockIdx.x * blockDim.x + threadIdx.x;
    if (i < N_EDGES) atomicAdd(&g_count[dst[i]], 1);
}

// ---------------- K3a: per-block sums (400 blocks x 256) -------------------
__global__ void k3a_bsum() {
    int t = threadIdx.x;
    int v = g_count[blockIdx.x * 256 + t];
    #pragma unroll
    for (int off = 16; off > 0; off >>= 1)
        v += __shfl_down_sync(0xffffffffu, v, off);
    __shared__ int ws[8];
    if ((t & 31) == 0) ws[t >> 5] = v;
    __syncthreads();
    if (t == 0) {
        int s = 0;
        #pragma unroll
        for (int w = 0; w < 8; w++) s += ws[w];
        g_bsum[blockIdx.x] = s;
    }
}

// ---------------- K3b: scan 400 block sums (1 block) -----------------------
__global__ void k3b_scan() {
    __shared__ int sh[512];
    int t = threadIdx.x;
    int v = (t < 400) ? g_bsum[t] : 0;
    sh[t] = v;
    __syncthreads();
    for (int off = 1; off < 512; off <<= 1) {
        int u = (t >= off) ? sh[t - off] : 0;
        __syncthreads();
        sh[t] += u;
        __syncthreads();
    }
    if (t < 400) g_boff[t] = sh[t] - v;   // exclusive
}

// ---------------- K3c: local exclusive scan, write rowptr/cursor -----------
__global__ void k3c_local() {
    int t = threadIdx.x, lane = t & 31, wid = t >> 5;
    int i = blockIdx.x * 256 + t;
    int v = g_count[i];
    int inc = v;
    #pragma unroll
    for (int off = 1; off < 32; off <<= 1) {
        int u = __shfl_up_sync(0xffffffffu, inc, off);
        if (lane >= off) inc += u;
    }
    __shared__ int wsum[8];
    if (lane == 31) wsum[wid] = inc;
    __syncthreads();
    if (t == 0) {
        int run = 0;
        #pragma unroll
        for (int w = 0; w < 8; w++) { int c = wsum[w]; wsum[w] = run; run += c; }
    }
    __syncthreads();
    int excl = inc - v + wsum[wid] + g_boff[blockIdx.x];
    g_rowptr[i] = excl;
    g_cursor[i] = excl;
    if (i == N_NODES - 1) g_rowptr[N_NODES] = excl + v;
}

// ---------------- K4: scatter edge srcs into CSR by dst --------------------
__global__ void k4_scatter(const int* __restrict__ src, const int* __restrict__ dst) {
    int i = blockIdx.x * blockDim.x + threadIdx.x;
    if (i < N_EDGES) {
        int d = dst[i];
        int p = atomicAdd(&g_cursor[d], 1);
        g_esrc[p] = src[i];
    }
}

// ---------------- K5: GAT1 edge aggregation + softmax + tanh (warp/dst) ----
__global__ void k5_agg1(const float* __restrict__ b1) {
    int gw   = (blockIdx.x * blockDim.x + threadIdx.x) >> 5;
    int lane = threadIdx.x & 31;
    if (gw >= N_NODES) return;
    int d = gw;

    float adv = (lane < 6) ? g_ad1[d * 6 + lane] : 0.f;
    int hA = lane >> 3;           // head for features 2lane,2lane+1   (0..3)
    int hB = 4 + (lane >> 3);     // head for features 64+2lane,..     (valid lane<16)

    float a0x = 0.f, a0y = 0.f, a1x = 0.f, a1y = 0.f, den = 0.f;
    int beg = g_rowptr[d], end = g_rowptr[d + 1];

    for (int e = beg - 1; e < end; ++e) {       // e == beg-1 -> self loop
        int s = (e < beg) ? d : g_esrc[e];
        float asv = (lane < 6) ? g_as1[s * 6 + lane] : 0.f;
        float wl  = __expf(lrelu02(asv + adv));
        if (lane < 6) den += wl;
        float wA = __shfl_sync(0xffffffffu, wl, hA);
        float wB = __shfl_sync(0xffffffffu, wl, hB & 7 ? hB : hB); // hB (4..7; 6,7 unused lanes)
        const __half2* hp = g_h1 + (size_t)s * 48;
        float2 f0 = __half22float2(hp[lane]);
        float2 f1 = __half22float2(hp[32 + lane]);  // lanes>=16 read pad/next row; unused
        a0x += wA * f0.x; a0y += wA * f0.y;
        a1x += wB * f1.x; a1y += wB * f1.y;
    }
    float dA = __shfl_sync(0xffffffffu, den, hA);
    float dB = __shfl_sync(0xffffffffu, den, hB);

    float* out = g_t1 + (size_t)d * 96;
    float rA = __fdividef(1.f, dA);
    out[2 * lane]     = tanh_f(a0x * rA + b1[2 * lane]);
    out[2 * lane + 1] = tanh_f(a0y * rA + b1[2 * lane + 1]);
    if (lane < 16) {
        float rB = __fdividef(1.f, dB);
        out[64 + 2 * lane]     = tanh_f(a1x * rB + b1[64 + 2 * lane]);
        out[64 + 2 * lane + 1] = tanh_f(a1y * rB + b1[64 + 2 * lane + 1]);
    }
}

// ---------------- K6: GAT2 node transform: h2 = t1@W2.T, attn dots ---------
__global__ void k6_node2(const float* __restrict__ W2,   // [32,96]
                         const float* __restrict__ as2w, // [1,32]
                         const float* __restrict__ ad2w) // [1,32]
{
    __shared__ float sWt[96 * 32];
    __shared__ float sas[32], sad[32];
    int tid = threadIdx.x;
    for (int i = tid; i < 3072; i += blockDim.x) {
        int j = i / 96, k = i % 96;
        sWt[k * 32 + j] = W2[i];
    }
    if (tid < 32) { sas[tid] = as2w[tid]; sad[tid] = ad2w[tid]; }
    __syncthreads();

    int n = blockIdx.x * blockDim.x + tid;
    if (n >= N_NODES) return;

    float acc[32];
    #pragma unroll
    for (int j = 0; j < 32; j++) acc[j] = 0.f;

    const float4* trow = (const float4*)(g_t1 + (size_t)n * 96);
    #pragma unroll 2
    for (int k4 = 0; k4 < 24; k4++) {
        float4 tv = trow[k4];
        int k = k4 * 4;
        #pragma unroll
        for (int j = 0; j < 32; j++) acc[j] += tv.x * sWt[(k + 0) * 32 + j];
        #pragma unroll
        for (int j = 0; j < 32; j++) acc[j] += tv.y * sWt[(k + 1) * 32 + j];
        #pragma unroll
        for (int j = 0; j < 32; j++) acc[j] += tv.z * sWt[(k + 2) * 32 + j];
        #pragma unroll
        for (int j = 0; j < 32; j++) acc[j] += tv.w * sWt[(k + 3) * 32 + j];
    }

    float as = 0.f, ad = 0.f;
    #pragma unroll
    for (int j = 0; j < 32; j++) { as += acc[j] * sas[j]; ad += acc[j] * sad[j]; }

    float* h2 = g_h2 + (size_t)n * 32;
    #pragma unroll
    for (int q = 0; q < 8; q++) {
        float4 o = make_float4(acc[4*q], acc[4*q+1], acc[4*q+2], acc[4*q+3]);
        ((float4*)h2)[q] = o;
    }
    g_as2[n] = as;
    g_ad2[n] = ad;
}

// ---------------- K7: GAT2 aggregation at robot nodes only (warp/robot) ----
__global__ void k7_agg2(const int* __restrict__ robot_index,
                        const float* __restrict__ b2) {
    int gw   = (blockIdx.x * blockDim.x + threadIdx.x) >> 5;
    int lane = threadIdx.x & 31;
    if (gw >= BATCH) return;
    int r = robot_index[gw];

    float adv = g_ad2[r];
    float acc = 0.f, den = 0.f;
    int beg = g_rowptr[r], end = g_rowptr[r + 1];
    for (int e = beg - 1; e < end; ++e) {
        int s = (e < beg) ? r : g_esrc[e];
        float w = __expf(lrelu02(g_as2[s] + adv));
        den += w;
        acc += w * g_h2[(size_t)s * 32 + lane];
    }
    g_out2[gw * 32 + lane] = acc / den + b2[lane];
}

// ---------------- K8: fc1 (tanh) + GRU input gates GI (per robot) ----------
__global__ void k8_fc1_gi(const float* __restrict__ robot_feat, // [B,4]
                          const float* __restrict__ fc1W,       // [64,36]
                          const float* __restrict__ fc1b,       // [64]
                          const float* __restrict__ wih,        // [192,64]
                          const float* __restrict__ bih)        // [192]
{
    __shared__ float s_in[36];
    __shared__ float s_x[64];
    int b = blockIdx.x, tid = threadIdx.x;
    if (tid < 32)       s_in[tid] = g_out2[b * 32 + tid];
    else if (tid < 36)  s_in[tid] = robot_feat[b * 4 + (tid - 32)];
    __syncthreads();
    if (tid < 64) {
        float a = fc1b[tid];
        const float* wr = fc1W + tid * 36;
        #pragma unroll
        for (int k = 0; k < 36; k++) a += s_in[k] * wr[k];
        s_x[tid] = tanh_f(a);
    }
    __syncthreads();
    {
        float a = bih[tid];
        const float* wr = wih + tid * 64;
        #pragma unroll 8
        for (int k = 0; k < 64; k++) a += s_x[k] * wr[k];
        g_GI[b * 192 + tid] = a;
    }
}

// ---------------- K9: sequential GRU over 1024 steps (1 block) -------------
__global__ void __launch_bounds__(192, 1) k9_gru(const float* __restrict__ whh, // [192,64]
                                                 const float* __restrict__ bhh) // [192]
{
    __shared__ __align__(16) float s_h[64];
    __shared__ float s_r[64], s_z[64], s_in[64], s_hn[64];
    int j = threadIdx.x;

    // packed weights: 32 x f32x2
    u64 wp[32];
    const float2* wr = (const float2*)(whh + j * 64);
    #pragma unroll
    for (int k = 0; k < 32; k++) { float2 f = wr[k]; wp[k] = pack2(f.x, f.y); }
    float bh = bhh[j];

    float hp = 0.f;
    if (j < 64) s_h[j] = 0.f;
    float gi_cur = g_GI[j];   // t = 0 prefetch
    __syncthreads();

    const float4* h4 = (const float4*)s_h;
    for (int t = 0; t < BATCH; t++) {
        float gi = gi_cur;
        if (t + 1 < BATCH) gi_cur = g_GI[(t + 1) * 192 + j];   // hide L2 latency

        u64 a0 = 0, a1 = 0, a2 = 0, a3 = 0;
        #pragma unroll
        for (int k = 0; k < 16; k++) {
            float4 hv = h4[k];
            u64 lo = pack2(hv.x, hv.y);
            u64 hi = pack2(hv.z, hv.w);
            if (k & 1) { fma2(a2, lo, wp[2 * k]); fma2(a3, hi, wp[2 * k + 1]); }
            else       { fma2(a0, lo, wp[2 * k]); fma2(a1, hi, wp[2 * k + 1]); }
        }
        float gh = (sum2(a0) + sum2(a1)) + (sum2(a2) + sum2(a3)) + bh;

        if (j < 64)          s_r[j]        = sigm_f(gi + gh);
        else if (j < 128)    s_z[j - 64]   = sigm_f(gi + gh);
        else               { s_in[j - 128] = gi; s_hn[j - 128] = gh; }
        __syncthreads();

        if (j < 64) {
            float ng = tanh_f(s_in[j] + s_r[j] * s_hn[j]);
            float z  = s_z[j];
            hp = (1.f - z) * ng + z * hp;
            g_HS[t * 64 + j] = hp;
            s_h[j] = hp;
        }
        __syncthreads();
    }
}

// ---------------- K10: fc2 -------------------------------------------------
__global__ void k10_fc2(const float* __restrict__ W,  // [11,64]
                        const float* __restrict__ b,  // [11]
                        float* __restrict__ out) {
    int i = blockIdx.x * blockDim.x + threadIdx.x;
    if (i >= BATCH * 11) return;
    int bb = i / 11, o = i % 11;
    float a = b[o];
    const float* hr = g_HS + bb * 64;
    const float* wr = W + o * 64;
    #pragma unroll
    for (int k = 0; k < 64; k++) a += hr[k] * wr[k];
    out[i] = a;
}

// ---------------- launch ----------------------------------------------------
extern "C" void kernel_launch(void* const* d_in, const int* in_sizes, int n_in,
                              void* d_out, int out_size) {
    const float* x              = (const float*)d_in[0];
    const int*   ei             = (const int*)  d_in[1];
    const int*   src            = ei;
    const int*   dst            = ei + N_EDGES;
    const int*   robot_index    = (const int*)  d_in[2];
    const float* robot_features = (const float*)d_in[3];
    const float* c1_W  = (const float*)d_in[4];
    const float* c1_as = (const float*)d_in[5];
    const float* c1_ad = (const float*)d_in[6];
    const float* c1_b  = (const float*)d_in[7];
    const float* c2_W  = (const float*)d_in[8];
    const float* c2_as = (const float*)d_in[9];
    const float* c2_ad = (const float*)d_in[10];
    const float* c2_b  = (const float*)d_in[11];
    const float* fc1_W = (const float*)d_in[12];
    const float* fc1_b = (const float*)d_in[13];
    const float* gru_wih = (const float*)d_in[14];
    const float* gru_whh = (const float*)d_in[15];
    const float* gru_bih = (const float*)d_in[16];
    const float* gru_bhh = (const float*)d_in[17];
    const float* fc2_W = (const float*)d_in[18];
    const float* fc2_b = (const float*)d_in[19];
    float* out = (float*)d_out;

    k1_node1  <<<(N_NODES + 127) / 128, 128>>>(x, c1_W, c1_as, c1_ad);
    k2_count  <<<(N_EDGES + 255) / 256, 256>>>(dst);
    k3a_bsum  <<<400, 256>>>();
    k3b_scan  <<<1, 512>>>();
    k3c_local <<<400, 256>>>();
    k4_scatter<<<(N_EDGES + 255) / 256, 256>>>(src, dst);
    k5_agg1   <<<(N_NODES * 32 + 255) / 256, 256>>>(c1_b);
    k6_node2  <<<(N_NODES + 255) / 256, 256>>>(c2_W, c2_as, c2_ad);
    k7_agg2   <<<(BATCH * 32 + 255) / 256, 256>>>(robot_index, c2_b);
    k8_fc1_gi <<<BATCH, 192>>>(robot_features, fc1_W, fc1_b, gru_wih, gru_bih);
    k9_gru    <<<1, 192>>>(gru_whh, gru_bhh);
    k10_fc2   <<<(BATCH * 11 + 255) / 256, 256>>>(fc2_W, fc2_b, out);
}

// round 3
// speedup vs baseline: 1.7423x; 1.3204x over previous
#include <cuda_runtime.h>
#include <cuda_fp16.h>
#include <cstdint>

#define N_NODES 102400
#define N_EDGES 1638400
#define BATCH   1024

typedef unsigned long long u64;
typedef unsigned int u32;

// ---------------- scratch (device globals) ----------------------------------
__device__ __half2 g_h1 [N_NODES * 48 + 64];
__device__ float g_as1[N_NODES * 6];
__device__ float g_ad1[N_NODES * 6];
__device__ float g_t1 [N_NODES * 96];
__device__ float g_h2 [N_NODES * 32];
__device__ float g_as2[N_NODES];
__device__ float g_ad2[N_NODES];
__device__ unsigned char g_flag   [N_NODES];
__device__ unsigned char g_isrobot[N_NODES];
__device__ int   g_count [N_NODES];
__device__ int   g_bsum  [400];
__device__ int   g_boff  [400];
__device__ int   g_rowptr[N_NODES + 1];
__device__ int   g_cursor[N_NODES];
__device__ int   g_esrc  [N_EDGES];
__device__ int   g_list  [N_NODES];
__device__ int   g_nS;
__device__ float g_out2[BATCH * 32];
__device__ float g_GI  [BATCH * 192];
__device__ float g_HS  [BATCH * 64];

// ---------------- math helpers ----------------------------------------------
__device__ __forceinline__ float sigm_f(float x) {
    return 1.0f / (1.0f + __expf(-x));
}
__device__ __forceinline__ float tanh_f(float x) {
    float cx = fminf(fmaxf(x, -15.0f), 15.0f);
    float e  = __expf(2.0f * cx);
    return __fdividef(e - 1.0f, e + 1.0f);
}
__device__ __forceinline__ float tanh_fast(float x) {
    float y; asm("tanh.approx.f32 %0, %1;" : "=f"(y) : "f"(x)); return y;
}
__device__ __forceinline__ float lrelu02(float x) {
    return x > 0.0f ? x : 0.2f * x;
}
__device__ __forceinline__ u64 pack2(float x, float y) {
    u64 r;
    asm("mov.b64 %0, {%1, %2};" : "=l"(r) : "f"(x), "f"(y));
    return r;
}
__device__ __forceinline__ void fma2(u64& acc, u64 a, u64 b) {
    asm("fma.rn.f32x2 %0, %1, %2, %0;" : "+l"(acc) : "l"(a), "l"(b));
}
__device__ __forceinline__ float sum2(u64 v) {
    float x, y;
    asm("mov.b64 {%0, %1}, %2;" : "=f"(x), "=f"(y) : "l"(v));
    return x + y;
}

// ---------------- K1: GAT1 node transform (fp16 out) + zero scratch ---------
__global__ void k1_node1(const float* __restrict__ x,
                         const float* __restrict__ W,   // [96,4]
                         const float* __restrict__ as_, // [6,16]
                         const float* __restrict__ ad_) // [6,16]
{
    __shared__ float sW[384], sas[96], sad[96];
    int tid = threadIdx.x;
    for (int i = tid; i < 384; i += blockDim.x) sW[i] = W[i];
    for (int i = tid; i < 96;  i += blockDim.x) { sas[i] = as_[i]; sad[i] = ad_[i]; }
    __syncthreads();

    int n = blockIdx.x * blockDim.x + tid;
    if (n >= N_NODES) return;
    g_count[n] = 0;
    g_flag[n] = 0;
    g_isrobot[n] = 0;
    if (n == 0) g_nS = 0;

    float4 xv = *(const float4*)(x + (size_t)n * 4);
    __half2 hbuf[48];

    #pragma unroll
    for (int h = 0; h < 6; h++) {
        float accs = 0.f, accd = 0.f;
        #pragma unroll
        for (int f = 0; f < 16; f += 2) {
            int j0 = h * 16 + f, j1 = j0 + 1;
            float v0 = xv.x*sW[j0*4+0] + xv.y*sW[j0*4+1] + xv.z*sW[j0*4+2] + xv.w*sW[j0*4+3];
            float v1 = xv.x*sW[j1*4+0] + xv.y*sW[j1*4+1] + xv.z*sW[j1*4+2] + xv.w*sW[j1*4+3];
            accs += v0 * sas[j0] + v1 * sas[j1];
            accd += v0 * sad[j0] + v1 * sad[j1];
            hbuf[(h * 16 + f) >> 1] = __floats2half2_rn(v0, v1);
        }
        g_as1[n * 6 + h] = accs;
        g_ad1[n * 6 + h] = accd;
    }
    float4* dst4 = (float4*)(g_h1 + (size_t)n * 48);
    const float4* src4 = (const float4*)hbuf;
    #pragma unroll
    for (int q = 0; q < 12; q++) dst4[q] = src4[q];
}

// ---------------- KR: mark robot nodes ---------------------------------------
__global__ void kR_robots(const int* __restrict__ robot_index) {
    int i = blockIdx.x * blockDim.x + threadIdx.x;
    if (i < BATCH) {
        int r = robot_index[i];
        g_isrobot[r] = 1;
        g_flag[r] = 1;    // robots are in S
    }
}

// ---------------- KA: mark sources of edges into robots (-> S) ---------------
__global__ void kA_mark(const int* __restrict__ src, const int* __restrict__ dst) {
    int i = blockIdx.x * blockDim.x + threadIdx.x;
    if (i < N_EDGES) {
        int d = dst[i];
        if (g_isrobot[d]) g_flag[src[i]] = 1;
    }
}

// ---------------- KC: count in-edges of S nodes -------------------------------
__global__ void kC_count(const int* __restrict__ dst) {
    int i = blockIdx.x * blockDim.x + threadIdx.x;
    if (i < N_EDGES) {
        int d = dst[i];
        if (g_flag[d]) atomicAdd(&g_count[d], 1);
    }
}

// ---------------- K3a/b/c: hierarchical exclusive scan ------------------------
__global__ void k3a_bsum() {
    int t = threadIdx.x;
    int v = g_count[blockIdx.x * 256 + t];
    #pragma unroll
    for (int off = 16; off > 0; off >>= 1)
        v += __shfl_down_sync(0xffffffffu, v, off);
    __shared__ int ws[8];
    if ((t & 31) == 0) ws[t >> 5] = v;
    __syncthreads();
    if (t == 0) {
        int s = 0;
        #pragma unroll
        for (int w = 0; w < 8; w++) s += ws[w];
        g_bsum[blockIdx.x] = s;
    }
}

__global__ void k3b_scan() {
    __shared__ int sh[512];
    int t = threadIdx.x;
    int v = (t < 400) ? g_bsum[t] : 0;
    sh[t] = v;
    __syncthreads();
    for (int off = 1; off < 512; off <<= 1) {
        int u = (t >= off) ? sh[t - off] : 0;
        __syncthreads();
        sh[t] += u;
        __syncthreads();
    }
    if (t < 400) g_boff[t] = sh[t] - v;   // exclusive
}

__global__ void k3c_local() {
    int t = threadIdx.x, lane = t & 31, wid = t >> 5;
    int i = blockIdx.x * 256 + t;
    int v = g_count[i];
    int inc = v;
    #pragma unroll
    for (int off = 1; off < 32; off <<= 1) {
        int u = __shfl_up_sync(0xffffffffu, inc, off);
        if (lane >= off) inc += u;
    }
    __shared__ int wsum[8];
    if (lane == 31) wsum[wid] = inc;
    __syncthreads();
    if (t == 0) {
        int run = 0;
        #pragma unroll
        for (int w = 0; w < 8; w++) { int c = wsum[w]; wsum[w] = run; run += c; }
    }
    __syncthreads();
    int excl = inc - v + wsum[wid] + g_boff[blockIdx.x];
    g_rowptr[i] = excl;
    g_cursor[i] = excl;
    if (i == N_NODES - 1) g_rowptr[N_NODES] = excl + v;
}

// ---------------- K4: scatter S-edges into CSR --------------------------------
__global__ void k4_scatter(const int* __restrict__ src, const int* __restrict__ dst) {
    int i = blockIdx.x * blockDim.x + threadIdx.x;
    if (i < N_EDGES) {
        int d = dst[i];
        if (g_flag[d]) {
            int p = atomicAdd(&g_cursor[d], 1);
            g_esrc[p] = src[i];
        }
    }
}

// ---------------- KW: compact S into worklist ---------------------------------
__global__ void kW_compact() {
    int n = blockIdx.x * blockDim.x + threadIdx.x;
    if (n < N_NODES && g_flag[n]) {
        int p = atomicAdd(&g_nS, 1);
        g_list[p] = n;
    }
}

// ---------------- K5: GAT1 aggregation + softmax + tanh (warp per S-node) ----
__global__ void k5_agg1(const float* __restrict__ b1) {
    int lane  = threadIdx.x & 31;
    int warpg = (blockIdx.x * blockDim.x + threadIdx.x) >> 5;
    int nwarp = (gridDim.x * blockDim.x) >> 5;
    int nS = g_nS;

    int hA = lane >> 3;           // head for features 2lane,2lane+1   (0..3)
    int hB = 4 + (lane >> 3);     // head for features 64+2lane (lane<16)

    for (int w = warpg; w < nS; w += nwarp) {
        int d = g_list[w];
        float adv = (lane < 6) ? g_ad1[d * 6 + lane] : 0.f;

        float a0x = 0.f, a0y = 0.f, a1x = 0.f, a1y = 0.f, den = 0.f;
        int beg = g_rowptr[d], end = g_rowptr[d + 1];

        for (int e = beg - 1; e < end; ++e) {       // e == beg-1 -> self loop
            int s = (e < beg) ? d : g_esrc[e];
            float asv = (lane < 6) ? g_as1[s * 6 + lane] : 0.f;
            float wl  = __expf(lrelu02(asv + adv));
            if (lane < 6) den += wl;
            float wA = __shfl_sync(0xffffffffu, wl, hA);
            float wB = __shfl_sync(0xffffffffu, wl, hB);
            const __half2* hp = g_h1 + (size_t)s * 48;
            float2 f0 = __half22float2(hp[lane]);
            float2 f1 = __half22float2(hp[32 + lane]);  // lanes>=16: pad reads, unused
            a0x += wA * f0.x; a0y += wA * f0.y;
            a1x += wB * f1.x; a1y += wB * f1.y;
        }
        float dA = __shfl_sync(0xffffffffu, den, hA);
        float dB = __shfl_sync(0xffffffffu, den, hB);

        float* out = g_t1 + (size_t)d * 96;
        float rA = __fdividef(1.f, dA);
        out[2 * lane]     = tanh_f(a0x * rA + b1[2 * lane]);
        out[2 * lane + 1] = tanh_f(a0y * rA + b1[2 * lane + 1]);
        if (lane < 16) {
            float rB = __fdividef(1.f, dB);
            out[64 + 2 * lane]     = tanh_f(a1x * rB + b1[64 + 2 * lane]);
            out[64 + 2 * lane + 1] = tanh_f(a1y * rB + b1[64 + 2 * lane + 1]);
        }
    }
}

// ---------------- K6: GAT2 node transform on S only ---------------------------
__global__ void k6_node2(const float* __restrict__ W2,   // [32,96]
                         const float* __restrict__ as2w, // [1,32]
                         const float* __restrict__ ad2w) // [1,32]
{
    __shared__ float sWt[96 * 32];
    __shared__ float sas[32], sad[32];
    int tid = threadIdx.x;
    for (int i = tid; i < 3072; i += blockDim.x) {
        int j = i / 96, k = i % 96;
        sWt[k * 32 + j] = W2[i];
    }
    if (tid < 32) { sas[tid] = as2w[tid]; sad[tid] = ad2w[tid]; }
    __syncthreads();

    int nS = g_nS;
    int stride = gridDim.x * blockDim.x;
    for (int idx = blockIdx.x * blockDim.x + tid; idx < nS; idx += stride) {
        int n = g_list[idx];

        float acc[32];
        #pragma unroll
        for (int j = 0; j < 32; j++) acc[j] = 0.f;

        const float4* trow = (const float4*)(g_t1 + (size_t)n * 96);
        #pragma unroll 2
        for (int k4 = 0; k4 < 24; k4++) {
            float4 tv = trow[k4];
            int k = k4 * 4;
            #pragma unroll
            for (int j = 0; j < 32; j++) acc[j] += tv.x * sWt[(k + 0) * 32 + j];
            #pragma unroll
            for (int j = 0; j < 32; j++) acc[j] += tv.y * sWt[(k + 1) * 32 + j];
            #pragma unroll
            for (int j = 0; j < 32; j++) acc[j] += tv.z * sWt[(k + 2) * 32 + j];
            #pragma unroll
            for (int j = 0; j < 32; j++) acc[j] += tv.w * sWt[(k + 3) * 32 + j];
        }

        float as = 0.f, ad = 0.f;
        #pragma unroll
        for (int j = 0; j < 32; j++) { as += acc[j] * sas[j]; ad += acc[j] * sad[j]; }

        float* h2 = g_h2 + (size_t)n * 32;
        #pragma unroll
        for (int q = 0; q < 8; q++)
            ((float4*)h2)[q] = make_float4(acc[4*q], acc[4*q+1], acc[4*q+2], acc[4*q+3]);
        g_as2[n] = as;
        g_ad2[n] = ad;
    }
}

// ---------------- K7: GAT2 aggregation at robot nodes (warp per robot) -------
__global__ void k7_agg2(const int* __restrict__ robot_index,
                        const float* __restrict__ b2) {
    int gw   = (blockIdx.x * blockDim.x + threadIdx.x) >> 5;
    int lane = threadIdx.x & 31;
    if (gw >= BATCH) return;
    int r = robot_index[gw];

    float adv = g_ad2[r];
    float acc = 0.f, den = 0.f;
    int beg = g_rowptr[r], end = g_rowptr[r + 1];
    for (int e = beg - 1; e < end; ++e) {
        int s = (e < beg) ? r : g_esrc[e];
        float w = __expf(lrelu02(g_as2[s] + adv));
        den += w;
        acc += w * g_h2[(size_t)s * 32 + lane];
    }
    g_out2[gw * 32 + lane] = acc / den + b2[lane];
}

// ---------------- K8: fc1 (tanh) + GRU input gates GI -------------------------
__global__ void k8_fc1_gi(const float* __restrict__ robot_feat, // [B,4]
                          const float* __restrict__ fc1W,       // [64,36]
                          const float* __restrict__ fc1b,       // [64]
                          const float* __restrict__ wih,        // [192,64]
                          const float* __restrict__ bih)        // [192]
{
    __shared__ float s_in[36];
    __shared__ float s_x[64];
    int b = blockIdx.x, tid = threadIdx.x;
    if (tid < 32)       s_in[tid] = g_out2[b * 32 + tid];
    else if (tid < 36)  s_in[tid] = robot_feat[b * 4 + (tid - 32)];
    __syncthreads();
    if (tid < 64) {
        float a = fc1b[tid];
        const float* wr = fc1W + tid * 36;
        #pragma unroll
        for (int k = 0; k < 36; k++) a += s_in[k] * wr[k];
        s_x[tid] = tanh_f(a);
    }
    __syncthreads();
    {
        float a = bih[tid];
        const float* wr = wih + tid * 64;
        #pragma unroll 8
        for (int k = 0; k < 64; k++) a += s_x[k] * wr[k];
        g_GI[b * 192 + tid] = a;
    }
}

// ---------------- K9: sequential GRU over 1024 steps (1 block) ---------------
__global__ void __launch_bounds__(192, 1) k9_gru(const float* __restrict__ whh, // [192,64]
                                                 const float* __restrict__ bhh) // [192]
{
    __shared__ __align__(16) float s_h[64];
    __shared__ float s_r[64], s_z[64], s_gin[64], s_hn[64];
    int j = threadIdx.x;
    // remap: warps 2,3 (solo on their SMSPs) own the r-gate + h update
    int row = (j < 64) ? (j + 64) : (j < 128 ? j - 64 : j);

    u64 wp[32];
    const float2* wr = (const float2*)(whh + row * 64);
    #pragma unroll
    for (int k = 0; k < 32; k++) { float2 f = wr[k]; wp[k] = pack2(f.x, f.y); }
    float bh = bhh[row];

    float hp = 0.f;
    if (j < 64) s_h[j] = 0.f;
    u32 hb = (u32)__cvta_generic_to_shared(s_h);
    float gi_cur = g_GI[row];
    __syncthreads();

    for (int t = 0; t < BATCH; t++) {
        float gi = gi_cur;
        if (t + 1 < BATCH) gi_cur = g_GI[(t + 1) * 192 + row];

        u64 a0 = 0, a1 = 0, a2 = 0, a3 = 0;
        #pragma unroll
        for (int k = 0; k < 8; k++) {
            u64 p0, p1, p2, p3;
            asm volatile("ld.shared.v2.b64 {%0, %1}, [%2];"
                         : "=l"(p0), "=l"(p1) : "r"(hb + k * 32));
            asm volatile("ld.shared.v2.b64 {%0, %1}, [%2];"
                         : "=l"(p2), "=l"(p3) : "r"(hb + k * 32 + 16));
            fma2(a0, p0, wp[4 * k + 0]);
            fma2(a1, p1, wp[4 * k + 1]);
            fma2(a2, p2, wp[4 * k + 2]);
            fma2(a3, p3, wp[4 * k + 3]);
        }
        float gh = (sum2(a0) + sum2(a1)) + (sum2(a2) + sum2(a3)) + bh;
        float g = gi + gh;

        if (j < 64)        s_z[j]       = sigm_f(g);
        else if (j < 128)  s_r[j - 64]  = sigm_f(g);
        else             { s_gin[j - 128] = gi; s_hn[j - 128] = gh; }
        __syncthreads();

        if (j >= 64 && j < 128) {
            int u = j - 64;
            float ng = tanh_fast(s_gin[u] + s_r[u] * s_hn[u]);
            float z  = s_z[u];
            hp = ng + z * (hp - ng);
            g_HS[t * 64 + u] = hp;
            s_h[u] = hp;
        }
        __syncthreads();
    }
}

// ---------------- K10: fc2 ----------------------------------------------------
__global__ void k10_fc2(const float* __restrict__ W,  // [11,64]
                        const float* __restrict__ b,  // [11]
                        float* __restrict__ out) {
    int i = blockIdx.x * blockDim.x + threadIdx.x;
    if (i >= BATCH * 11) return;
    int bb = i / 11, o = i % 11;
    float a = b[o];
    const float* hr = g_HS + bb * 64;
    const float* wr = W + o * 64;
    #pragma unroll
    for (int k = 0; k < 64; k++) a += hr[k] * wr[k];
    out[i] = a;
}

// ---------------- launch ------------------------------------------------------
extern "C" void kernel_launch(void* const* d_in, const int* in_sizes, int n_in,
                              void* d_out, int out_size) {
    const float* x              = (const float*)d_in[0];
    const int*   ei             = (const int*)  d_in[1];
    const int*   src            = ei;
    const int*   dst            = ei + N_EDGES;
    const int*   robot_index    = (const int*)  d_in[2];
    const float* robot_features = (const float*)d_in[3];
    const float* c1_W  = (const float*)d_in[4];
    const float* c1_as = (const float*)d_in[5];
    const float* c1_ad = (const float*)d_in[6];
    const float* c1_b  = (const float*)d_in[7];
    const float* c2_W  = (const float*)d_in[8];
    const float* c2_as = (const float*)d_in[9];
    const float* c2_ad = (const float*)d_in[10];
    const float* c2_b  = (const float*)d_in[11];
    const float* fc1_W = (const float*)d_in[12];
    const float* fc1_b = (const float*)d_in[13];
    const float* gru_wih = (const float*)d_in[14];
    const float* gru_whh = (const float*)d_in[15];
    const float* gru_bih = (const float*)d_in[16];
    const float* gru_bhh = (const float*)d_in[17];
    const float* fc2_W = (const float*)d_in[18];
    const float* fc2_b = (const float*)d_in[19];
    float* out = (float*)d_out;

    k1_node1  <<<(N_NODES + 127) / 128, 128>>>(x, c1_W, c1_as, c1_ad);
    kR_robots <<<(BATCH + 255) / 256, 256>>>(robot_index);
    kA_mark   <<<(N_EDGES + 255) / 256, 256>>>(src, dst);
    kC_count  <<<(N_EDGES + 255) / 256, 256>>>(dst);
    k3a_bsum  <<<400, 256>>>();
    k3b_scan  <<<1, 512>>>();
    k3c_local <<<400, 256>>>();
    k4_scatter<<<(N_EDGES + 255) / 256, 256>>>(src, dst);
    kW_compact<<<400, 256>>>();
    k5_agg1   <<<512, 256>>>(c1_b);
    k6_node2  <<<128, 256>>>(c2_W, c2_as, c2_ad);
    k7_agg2   <<<(BATCH * 32 + 255) / 256, 256>>>(robot_index, c2_b);
    k8_fc1_gi <<<BATCH, 192>>>(robot_features, fc1_W, fc1_b, gru_wih, gru_bih);
    k9_gru    <<<1, 192>>>(gru_whh, gru_bhh);
    k10_fc2   <<<(BATCH * 11 + 255) / 256, 256>>>(fc2_W, fc2_b, out);
}